// round 16
// baseline (speedup 1.0000x reference)
#include <cuda_runtime.h>
#include <cuda_fp16.h>
#include <math_constants.h>

#define BB 16
#define TT 2048
#define CC 384
#define DD 64

// q fp32; K/V stored as fp16x2 with the two MMA B-operands paired into uint2
__device__ float g_q[BB * TT * DD];
// K: pair p (rows 8c+lr, 8c+lr+4 of the 32 d-pairs), [b][p 0..15][t 0..2047]
__device__ uint2 g_k2[BB * 16 * TT];
// V: per 64-t tile st, pair p of the 32 sp rows, [b][st 0..31][p 0..15][d 0..63]
__device__ uint2 g_v2[BB * 32 * 16 * DD];
// fused W packed fp16x2 (pairs along k): [kp 0..191][n 0..191]
__device__ unsigned g_wf[192 * 192];

// ---- helpers ------------------------------------------------------------
__device__ __forceinline__ unsigned packh2(float a, float b) {
    unsigned r;
    asm("cvt.rn.f16x2.f32 %0, %1, %2;" : "=r"(r) : "f"(b), "f"(a));
    return r;
}
__device__ __forceinline__ void splith2(float a, float b, unsigned& hi, unsigned& lo) {
    unsigned h;
    asm("cvt.rn.f16x2.f32 %0, %1, %2;" : "=r"(h) : "f"(b), "f"(a));
    __half2 hh = *reinterpret_cast<__half2*>(&h);
    float2 hf = __half22float2(hh);
    unsigned l;
    asm("cvt.rn.f16x2.f32 %0, %1, %2;" : "=r"(l) : "f"(b - hf.y), "f"(a - hf.x));
    hi = h; lo = l;
}
__device__ __forceinline__ unsigned h2exp2(unsigned x) {
    unsigned r;
    asm("ex2.approx.f16x2 %0, %1;" : "=r"(r) : "r"(x));
    return r;
}
__device__ __forceinline__ void mma16h(float4& c, const unsigned a[4],
                                       unsigned b0, unsigned b1) {
    asm("mma.sync.aligned.m16n8k16.row.col.f32.f16.f16.f32 "
        "{%0,%1,%2,%3},{%4,%5,%6,%7},{%8,%9},{%0,%1,%2,%3};"
        : "+f"(c.x), "+f"(c.y), "+f"(c.z), "+f"(c.w)
        : "r"(a[0]), "r"(a[1]), "r"(a[2]), "r"(a[3]), "r"(b0), "r"(b1));
}
__device__ __forceinline__ void cpa16(const void* smem_dst, const void* gsrc) {
    unsigned d = (unsigned)__cvta_generic_to_shared(smem_dst);
    asm volatile("cp.async.cg.shared.global [%0], [%1], 16;" :: "r"(d), "l"(gsrc));
}
__device__ __forceinline__ float ex2(float x) {
    float r;
    asm("ex2.approx.f32 %0, %1;" : "=f"(r) : "f"(x));
    return r;
}

// ---------------------------------------------------------------------------
// Kernel 0: one-shot W pack (fp16 pairs along k). 192 blocks x 192 threads.
// ---------------------------------------------------------------------------
__global__ void wsplit_kernel(const float* __restrict__ Wq,
                              const float* __restrict__ Wk,
                              const float* __restrict__ Wv)
{
    const int kp = blockIdx.x;
    const int n  = threadIdx.x;
    const float* W = (n < 64) ? Wq : (n < 128) ? Wk : Wv;
    const int c = n & 63;
    g_wf[kp * 192 + n] = packh2(W[(2 * kp) * DD + c], W[(2 * kp + 1) * DD + c]);
}

// ---------------------------------------------------------------------------
// Kernel 1: fused QKV projection, fp16 2-term mma (x hi/lo, W single fp16),
// double-buffered kstep=32. grid (256 row-blocks, 2 col-blocks of 96).
// 256 threads, 8 warps. Epilogue writes q fp32 and paired fp16 K/V layouts.
// ---------------------------------------------------------------------------
#define XS2 36
#define WS2 100
#define XBUF (128 * XS2)
#define WBUF (16 * WS2)
#define PROJ_SMEM ((2 * XBUF + 2 * WBUF) * 4)
#define NKS (CC / 32)

__global__ __launch_bounds__(256, 2) void proj_kernel(const float* __restrict__ x)
{
    extern __shared__ float psm[];
    float* xsb = psm;
    float* wfb = psm + 2 * XBUF;

    const int tid  = threadIdx.x;
    const int lane = tid & 31, warp = tid >> 5;
    const int lg = lane >> 2, lr = lane & 3;
    const int rowBase = blockIdx.x * 128;
    const int cb = blockIdx.y;

    auto stage = [&](int buf, int ks) {
        const int kk = ks * 32;
        float* xs = xsb + buf * XBUF;
        float* wf = wfb + buf * WBUF;
#pragma unroll
        for (int u = 0; u < 4; u++) {
            const int cid = tid + 256 * u;
            const int row = cid >> 3;
            const int off = (cid & 7) * 4;
            cpa16(xs + row * XS2 + off, x + (size_t)(rowBase + row) * CC + kk + off);
        }
#pragma unroll
        for (int u = 0; u < 2; u++) {
            const int cid = tid + 256 * u;
            if (cid < 384) {
                const int row = cid / 24;
                const int off = (cid % 24) * 4;
                cpa16(wf + row * WS2 + off, g_wf + (kk / 2 + row) * 192 + cb * 96 + off);
            }
        }
        asm volatile("cp.async.commit_group;" ::: "memory");
    };

    float4 acc[12];
#pragma unroll
    for (int j = 0; j < 12; j++) acc[j] = make_float4(0.f, 0.f, 0.f, 0.f);

    stage(0, 0);
    int buf = 0;

    for (int ks = 0; ks < NKS; ks++) {
        if (ks + 1 < NKS) {
            stage(buf ^ 1, ks + 1);
            asm volatile("cp.async.wait_group 1;" ::: "memory");
        } else {
            asm volatile("cp.async.wait_group 0;" ::: "memory");
        }
        __syncthreads();

        const float* xs = xsb + buf * XBUF;
        const float* wf = wfb + buf * WBUF;

#pragma unroll
        for (int c = 0; c < 2; c++) {
            unsigned ah[4], al[4];
            {
                const int rb0 = warp * 16 + lg;
                const int k0  = 16 * c + 2 * lr;
                float2 p0 = *(float2*)&xs[rb0 * XS2 + k0];
                float2 p1 = *(float2*)&xs[(rb0 + 8) * XS2 + k0];
                float2 p2 = *(float2*)&xs[rb0 * XS2 + k0 + 8];
                float2 p3 = *(float2*)&xs[(rb0 + 8) * XS2 + k0 + 8];
                splith2(p0.x, p0.y, ah[0], al[0]);
                splith2(p1.x, p1.y, ah[1], al[1]);
                splith2(p2.x, p2.y, ah[2], al[2]);
                splith2(p3.x, p3.y, ah[3], al[3]);
            }
#pragma unroll
            for (int j = 0; j < 12; j++) {
                const unsigned b0 = __float_as_uint(wf[(8 * c + lr) * WS2 + j * 8 + lg]);
                const unsigned b1 = __float_as_uint(wf[(8 * c + lr + 4) * WS2 + j * 8 + lg]);
                mma16h(acc[j], ah, b0, b1);
                mma16h(acc[j], al, b0, b1);
            }
        }
        __syncthreads();
        buf ^= 1;
    }

    // ---- epilogue: q(fp32) / K,V in paired uint2 layouts ----
    {
        const int r0 = rowBase + warp * 16 + lg;
        const int b  = r0 >> 11;
        const int t  = r0 & 2047;
#pragma unroll
        for (int j = 0; j < 12; j++) {
            const int gc = cb * 96 + j * 8 + 2 * lr;
            float4 a = acc[j];
            if (gc < 64) {
                *(float2*)&g_q[r0 * DD + gc]       = make_float2(a.x, a.y);
                *(float2*)&g_q[(r0 + 8) * DD + gc] = make_float2(a.z, a.w);
            } else if (gc < 128) {
                if ((j & 1) == 0) {
                    float4 a2 = acc[j + 1];
                    const int dp = (gc - 64) >> 1;
                    const int p  = ((dp >> 3) << 2) | lr;
                    uint2* dst = g_k2 + ((size_t)b * 16 + p) * 2048 + t;
                    dst[0] = make_uint2(packh2(a.x, a.y), packh2(a2.x, a2.y));
                    dst[8] = make_uint2(packh2(a.z, a.w), packh2(a2.z, a2.w));
                }
            } else {
                const int d = gc - 128;
                float ox = __shfl_xor_sync(0xffffffffu, a.x, 4);
                float oy = __shfl_xor_sync(0xffffffffu, a.y, 4);
                float oz = __shfl_xor_sync(0xffffffffu, a.z, 4);
                float ow = __shfl_xor_sync(0xffffffffu, a.w, 4);
                if ((lg & 1) == 0) {
                    const int sp_in_b = t >> 1;
                    const int st  = sp_in_b >> 5;
                    const int spl = sp_in_b & 31;
                    const int p   = ((spl >> 3) << 2) | (spl & 3);
                    uint2* dst = g_v2 + (((size_t)(b * 32 + st)) * 16 + p) * 64 + d;
                    *(uint4*)dst = make_uint4(packh2(a.x, ox), packh2(a.z, oz),
                                              packh2(a.y, oy), packh2(a.w, ow));
                }
            }
        }
    }
}

// ---------------------------------------------------------------------------
// Kernel 2: flash attention. QK: fp16 (Q hi/lo 2-term, K single). PV: fp16
// (P single via ex2.f16x2, V single). l via tensor-pipe ones-MMA.
// Paired uint2 K/V smem (LDS.64 B-fragments). Causal mask diag tile only.
// UNPAIRED grid: 512 CTAs (one 64-row q-tile each, longest-first) so the
// 3-CTA/SM occupancy limit is actually reached. 128-wide paired staging.
// ---------------------------------------------------------------------------
#define KP2 68
#define ARRU (16 * KP2)
#define ATTN_SMEM (8 * ARRU * 8)
#define ONESH2 0x3C003C00u

__global__ __launch_bounds__(128, 3) void attn_kernel(float* __restrict__ out)
{
    extern __shared__ uint2 sm2[];

    const int b    = blockIdx.y;
    const int qt   = 31 - blockIdx.x;      // longest first
    const int tid  = threadIdx.x;
    const int lane = tid & 31, warp = tid >> 5;
    const int lg = lane >> 2, lr = lane & 3;
    const int wrow = warp * 16;

    const float NEG_INF = -CUDART_INF_F;
    const float SCL = 0.125f * 1.44269504088896340736f;

    auto stage64 = [&](int slot, int st) {
        uint2* kf = sm2 + (slot * 2 + 0) * ARRU;
        uint2* vf = sm2 + (slot * 2 + 1) * ARRU;
        const uint2* gk = g_k2 + (size_t)b * 16 * 2048 + st * 64;
        const uint2* gv = g_v2 + ((size_t)(b * 32 + st)) * 16 * 64;
#pragma unroll
        for (int u = 0; u < 4; u++) {
            const int cid = tid + 128 * u;
            const int p   = cid >> 5;
            const int off = (cid & 31) * 2;
            cpa16(kf + p * KP2 + off, gk + p * 2048 + off);
            cpa16(vf + p * KP2 + off, gv + p * 64 + off);
        }
    };

    const int rowg = b * TT + qt * 64;
    const int grow1 = qt * 64 + wrow + lg;
    const int grow2 = grow1 + 8;

    // ---- Q fragments (prescaled by SCL, fp16 hi/lo split) ----
    unsigned qh[4][4], ql[4][4];
    {
        const float* q1 = g_q + (rowg + wrow + lg) * DD;
        const float* q2 = q1 + 8 * DD;
#pragma unroll
        for (int c = 0; c < 4; c++) {
            const int cc = 16 * c + 2 * lr;
            float2 a  = *(const float2*)(q1 + cc);
            float2 bq = *(const float2*)(q2 + cc);
            float2 a8 = *(const float2*)(q1 + cc + 8);
            float2 b8 = *(const float2*)(q2 + cc + 8);
            splith2(a.x  * SCL, a.y  * SCL, qh[c][0], ql[c][0]);
            splith2(bq.x * SCL, bq.y * SCL, qh[c][1], ql[c][1]);
            splith2(a8.x * SCL, a8.y * SCL, qh[c][2], ql[c][2]);
            splith2(b8.x * SCL, b8.y * SCL, qh[c][3], ql[c][3]);
        }
    }

    float4 oc[8];
#pragma unroll
    for (int j = 0; j < 8; j++) oc[j] = make_float4(0.f, 0.f, 0.f, 0.f);
    float4 ls = make_float4(0.f, 0.f, 0.f, 0.f);
    float m1 = -1e30f, m2 = -1e30f;

    auto process = [&](int slot, int st) {
        const uint2* kfb = sm2 + (slot * 2 + 0) * ARRU;
        const uint2* vfb = sm2 + (slot * 2 + 1) * ARRU;

        float4 sc[8];
#pragma unroll
        for (int j = 0; j < 8; j++) sc[j] = make_float4(0.f, 0.f, 0.f, 0.f);
#pragma unroll
        for (int c = 0; c < 4; c++) {
            const int kb = (4 * c + lr) * KP2 + lg;
#pragma unroll
            for (int j = 0; j < 8; j++) {
                const uint2 kk = kfb[kb + 8 * j];
                mma16h(sc[j], qh[c], kk.x, kk.y);
                mma16h(sc[j], ql[c], kk.x, kk.y);
            }
        }

        if (st == qt) {
            const int cbv = st * 64 + 2 * lr;
#pragma unroll
            for (int j = 0; j < 8; j++) {
                const int c0g = cbv + 8 * j;
                if (c0g     > grow1) sc[j].x = NEG_INF;
                if (c0g + 1 > grow1) sc[j].y = NEG_INF;
                if (c0g     > grow2) sc[j].z = NEG_INF;
                if (c0g + 1 > grow2) sc[j].w = NEG_INF;
            }
        }

        float rm1 = NEG_INF, rm2 = NEG_INF;
#pragma unroll
        for (int j = 0; j < 8; j++) {
            rm1 = fmaxf(rm1, fmaxf(sc[j].x, sc[j].y));
            rm2 = fmaxf(rm2, fmaxf(sc[j].z, sc[j].w));
        }
        rm1 = fmaxf(rm1, __shfl_xor_sync(0xffffffffu, rm1, 1));
        rm1 = fmaxf(rm1, __shfl_xor_sync(0xffffffffu, rm1, 2));
        rm2 = fmaxf(rm2, __shfl_xor_sync(0xffffffffu, rm2, 1));
        rm2 = fmaxf(rm2, __shfl_xor_sync(0xffffffffu, rm2, 2));

        const float mn1 = fmaxf(m1, rm1);
        const float mn2 = fmaxf(m2, rm2);
        const float fac1 = ex2(m1 - mn1);
        const float fac2 = ex2(m2 - mn2);
        m1 = mn1;
        m2 = mn2;

        unsigned pha[8], phb[8];
#pragma unroll
        for (int j = 0; j < 8; j++) {
            pha[j] = h2exp2(packh2(sc[j].x - mn1, sc[j].y - mn1));
            phb[j] = h2exp2(packh2(sc[j].z - mn2, sc[j].w - mn2));
        }

#pragma unroll
        for (int j = 0; j < 8; j++) {
            oc[j].x *= fac1; oc[j].y *= fac1;
            oc[j].z *= fac2; oc[j].w *= fac2;
        }
        ls.x *= fac1;
        ls.z *= fac2;

#pragma unroll
        for (int c = 0; c < 4; c++) {
            const unsigned ah[4] = {pha[2 * c], phb[2 * c], pha[2 * c + 1], phb[2 * c + 1]};
            const int vb = (4 * c + lr) * KP2 + lg;
#pragma unroll
            for (int j = 0; j < 8; j++) {
                const uint2 vv = vfb[vb + 8 * j];
                mma16h(oc[j], ah, vv.x, vv.y);
            }
            mma16h(ls, ah, ONESH2, ONESH2);
        }
    };

    const int npair = (qt + 2) >> 1;

    stage64(0, 0);
    stage64(1, 1);
    asm volatile("cp.async.commit_group;" ::: "memory");
    int buf = 0;

    for (int p = 0; p < npair; p++) {
        asm volatile("cp.async.wait_group 0;" ::: "memory");
        __syncthreads();
        if (p + 1 < npair) {
            const int s2 = 2 * (p + 1);
            stage64((buf ^ 1) * 2 + 0, s2);
            stage64((buf ^ 1) * 2 + 1, s2 + 1);
            asm volatile("cp.async.commit_group;" ::: "memory");
        }

        const int stA = 2 * p;
        process(buf * 2 + 0, stA);
        if (stA + 1 <= qt) process(buf * 2 + 1, stA + 1);
        buf ^= 1;
    }

    // ---- epilogue ----
    const float inv1 = 1.0f / ls.x;
    const float inv2 = 1.0f / ls.z;
    const int ob1 = (rowg + wrow + lg) * DD + 2 * lr;
    const int ob2 = ob1 + 8 * DD;
#pragma unroll
    for (int j = 0; j < 8; j++) {
        *(float2*)&out[ob1 + 8 * j] = make_float2(oc[j].x * inv1, oc[j].y * inv1);
        *(float2*)&out[ob2 + 8 * j] = make_float2(oc[j].z * inv2, oc[j].w * inv2);
    }
}

// ---------------------------------------------------------------------------
extern "C" void kernel_launch(void* const* d_in, const int* in_sizes, int n_in,
                              void* d_out, int out_size)
{
    (void)in_sizes; (void)n_in; (void)out_size;
    const float* x  = (const float*)d_in[0];
    const float* Wq = (const float*)d_in[1];
    const float* Wk = (const float*)d_in[2];
    const float* Wv = (const float*)d_in[3];
    float* out = (float*)d_out;

    cudaFuncSetAttribute(proj_kernel,
                         cudaFuncAttributeMaxDynamicSharedMemorySize, PROJ_SMEM);
    cudaFuncSetAttribute(attn_kernel,
                         cudaFuncAttributeMaxDynamicSharedMemorySize, ATTN_SMEM);

    wsplit_kernel<<<192, 192>>>(Wq, Wk, Wv);
    proj_kernel<<<dim3(BB * TT / 128, 2), 256, PROJ_SMEM>>>(x);
    attn_kernel<<<dim3(32, BB), 128, ATTN_SMEM>>>(out);
}

// round 17
// speedup vs baseline: 1.0437x; 1.0437x over previous
#include <cuda_runtime.h>
#include <cuda_fp16.h>
#include <math_constants.h>

#define BB 16
#define TT 2048
#define CC 384
#define DD 64

// q fp32; K/V stored as fp16x2 with the two MMA B-operands paired into uint2
__device__ float g_q[BB * TT * DD];
__device__ uint2 g_k2[BB * 16 * TT];           // [b][p 0..15][t]
__device__ uint2 g_v2[BB * 32 * 16 * DD];      // [b][st][p][d]
__device__ unsigned g_wf[192 * 192];           // W packed fp16x2 pairs along k

// ---- helpers ------------------------------------------------------------
__device__ __forceinline__ unsigned packh2(float a, float b) {
    unsigned r;
    asm("cvt.rn.f16x2.f32 %0, %1, %2;" : "=r"(r) : "f"(b), "f"(a));
    return r;
}
__device__ __forceinline__ void splith2(float a, float b, unsigned& hi, unsigned& lo) {
    unsigned h;
    asm("cvt.rn.f16x2.f32 %0, %1, %2;" : "=r"(h) : "f"(b), "f"(a));
    __half2 hh = *reinterpret_cast<__half2*>(&h);
    float2 hf = __half22float2(hh);
    unsigned l;
    asm("cvt.rn.f16x2.f32 %0, %1, %2;" : "=r"(l) : "f"(b - hf.y), "f"(a - hf.x));
    hi = h; lo = l;
}
__device__ __forceinline__ unsigned h2exp2(unsigned x) {
    unsigned r;
    asm("ex2.approx.f16x2 %0, %1;" : "=r"(r) : "r"(x));
    return r;
}
__device__ __forceinline__ void mma16h(float4& c, const unsigned a[4],
                                       unsigned b0, unsigned b1) {
    asm("mma.sync.aligned.m16n8k16.row.col.f32.f16.f16.f32 "
        "{%0,%1,%2,%3},{%4,%5,%6,%7},{%8,%9},{%0,%1,%2,%3};"
        : "+f"(c.x), "+f"(c.y), "+f"(c.z), "+f"(c.w)
        : "r"(a[0]), "r"(a[1]), "r"(a[2]), "r"(a[3]), "r"(b0), "r"(b1));
}
__device__ __forceinline__ void cpa16(const void* smem_dst, const void* gsrc) {
    unsigned d = (unsigned)__cvta_generic_to_shared(smem_dst);
    asm volatile("cp.async.cg.shared.global [%0], [%1], 16;" :: "r"(d), "l"(gsrc));
}
__device__ __forceinline__ float ex2(float x) {
    float r;
    asm("ex2.approx.f32 %0, %1;" : "=f"(r) : "f"(x));
    return r;
}

// ---------------------------------------------------------------------------
// Kernel 0: one-shot W pack. 192 blocks x 192 threads.
// ---------------------------------------------------------------------------
__global__ void wsplit_kernel(const float* __restrict__ Wq,
                              const float* __restrict__ Wk,
                              const float* __restrict__ Wv)
{
    const int kp = blockIdx.x;
    const int n  = threadIdx.x;
    const float* W = (n < 64) ? Wq : (n < 128) ? Wk : Wv;
    const int c = n & 63;
    g_wf[kp * 192 + n] = packh2(W[(2 * kp) * DD + c], W[(2 * kp + 1) * DD + c]);
}

// ---------------------------------------------------------------------------
// Kernel 1: fused QKV projection, fp16 2-term mma, double-buffered kstep=32.
// ---------------------------------------------------------------------------
#define XS2 36
#define WS2 100
#define XBUF (128 * XS2)
#define WBUF (16 * WS2)
#define PROJ_SMEM ((2 * XBUF + 2 * WBUF) * 4)
#define NKS (CC / 32)

__global__ __launch_bounds__(256, 2) void proj_kernel(const float* __restrict__ x)
{
    extern __shared__ float psm[];
    float* xsb = psm;
    float* wfb = psm + 2 * XBUF;

    const int tid  = threadIdx.x;
    const int lane = tid & 31, warp = tid >> 5;
    const int lg = lane >> 2, lr = lane & 3;
    const int rowBase = blockIdx.x * 128;
    const int cb = blockIdx.y;

    auto stage = [&](int buf, int ks) {
        const int kk = ks * 32;
        float* xs = xsb + buf * XBUF;
        float* wf = wfb + buf * WBUF;
#pragma unroll
        for (int u = 0; u < 4; u++) {
            const int cid = tid + 256 * u;
            const int row = cid >> 3;
            const int off = (cid & 7) * 4;
            cpa16(xs + row * XS2 + off, x + (size_t)(rowBase + row) * CC + kk + off);
        }
#pragma unroll
        for (int u = 0; u < 2; u++) {
            const int cid = tid + 256 * u;
            if (cid < 384) {
                const int row = cid / 24;
                const int off = (cid % 24) * 4;
                cpa16(wf + row * WS2 + off, g_wf + (kk / 2 + row) * 192 + cb * 96 + off);
            }
        }
        asm volatile("cp.async.commit_group;" ::: "memory");
    };

    float4 acc[12];
#pragma unroll
    for (int j = 0; j < 12; j++) acc[j] = make_float4(0.f, 0.f, 0.f, 0.f);

    stage(0, 0);
    int buf = 0;

    for (int ks = 0; ks < NKS; ks++) {
        if (ks + 1 < NKS) {
            stage(buf ^ 1, ks + 1);
            asm volatile("cp.async.wait_group 1;" ::: "memory");
        } else {
            asm volatile("cp.async.wait_group 0;" ::: "memory");
        }
        __syncthreads();

        const float* xs = xsb + buf * XBUF;
        const float* wf = wfb + buf * WBUF;

#pragma unroll
        for (int c = 0; c < 2; c++) {
            unsigned ah[4], al[4];
            {
                const int rb0 = warp * 16 + lg;
                const int k0  = 16 * c + 2 * lr;
                float2 p0 = *(float2*)&xs[rb0 * XS2 + k0];
                float2 p1 = *(float2*)&xs[(rb0 + 8) * XS2 + k0];
                float2 p2 = *(float2*)&xs[rb0 * XS2 + k0 + 8];
                float2 p3 = *(float2*)&xs[(rb0 + 8) * XS2 + k0 + 8];
                splith2(p0.x, p0.y, ah[0], al[0]);
                splith2(p1.x, p1.y, ah[1], al[1]);
                splith2(p2.x, p2.y, ah[2], al[2]);
                splith2(p3.x, p3.y, ah[3], al[3]);
            }
#pragma unroll
            for (int j = 0; j < 12; j++) {
                const unsigned b0 = __float_as_uint(wf[(8 * c + lr) * WS2 + j * 8 + lg]);
                const unsigned b1 = __float_as_uint(wf[(8 * c + lr + 4) * WS2 + j * 8 + lg]);
                mma16h(acc[j], ah, b0, b1);
                mma16h(acc[j], al, b0, b1);
            }
        }
        __syncthreads();
        buf ^= 1;
    }

    // ---- epilogue: q(fp32) / K,V in paired uint2 layouts ----
    {
        const int r0 = rowBase + warp * 16 + lg;
        const int b  = r0 >> 11;
        const int t  = r0 & 2047;
#pragma unroll
        for (int j = 0; j < 12; j++) {
            const int gc = cb * 96 + j * 8 + 2 * lr;
            float4 a = acc[j];
            if (gc < 64) {
                *(float2*)&g_q[r0 * DD + gc]       = make_float2(a.x, a.y);
                *(float2*)&g_q[(r0 + 8) * DD + gc] = make_float2(a.z, a.w);
            } else if (gc < 128) {
                if ((j & 1) == 0) {
                    float4 a2 = acc[j + 1];
                    const int dp = (gc - 64) >> 1;
                    const int p  = ((dp >> 3) << 2) | lr;
                    uint2* dst = g_k2 + ((size_t)b * 16 + p) * 2048 + t;
                    dst[0] = make_uint2(packh2(a.x, a.y), packh2(a2.x, a2.y));
                    dst[8] = make_uint2(packh2(a.z, a.w), packh2(a2.z, a2.w));
                }
            } else {
                const int d = gc - 128;
                float ox = __shfl_xor_sync(0xffffffffu, a.x, 4);
                float oy = __shfl_xor_sync(0xffffffffu, a.y, 4);
                float oz = __shfl_xor_sync(0xffffffffu, a.z, 4);
                float ow = __shfl_xor_sync(0xffffffffu, a.w, 4);
                if ((lg & 1) == 0) {
                    const int sp_in_b = t >> 1;
                    const int st  = sp_in_b >> 5;
                    const int spl = sp_in_b & 31;
                    const int p   = ((spl >> 3) << 2) | (spl & 3);
                    uint2* dst = g_v2 + (((size_t)(b * 32 + st)) * 16 + p) * 64 + d;
                    *(uint4*)dst = make_uint4(packh2(a.x, ox), packh2(a.z, oz),
                                              packh2(a.y, oy), packh2(a.w, ow));
                }
            }
        }
    }
}

// ---------------------------------------------------------------------------
// Kernel 2: flash attention. QK: fp16 (Q hi/lo 2-term, K single). PV: fp16.
// Staged pairs processed as ONE 128-wide softmax block: S_A + S_B first
// (ILP), then one joint max/rescale, then exp+PV per tile. Triangle-balanced
// CTA pairs (R15 grid), 3 CTAs/SM, 128-wide paired cp.async staging.
// ---------------------------------------------------------------------------
#define KP2 68
#define ARRU (16 * KP2)
#define ATTN_SMEM (8 * ARRU * 8)
#define ONESH2 0x3C003C00u

__global__ __launch_bounds__(128, 3) void attn_kernel(float* __restrict__ out)
{
    extern __shared__ uint2 sm2[];

    const int b    = blockIdx.y;
    const int tid  = threadIdx.x;
    const int lane = tid & 31, warp = tid >> 5;
    const int lg = lane >> 2, lr = lane & 3;
    const int wrow = warp * 16;

    const float NEG_INF = -CUDART_INF_F;
    const float SCL = 0.125f * 1.44269504088896340736f;

    auto stage64 = [&](int slot, int st) {
        uint2* kf = sm2 + (slot * 2 + 0) * ARRU;
        uint2* vf = sm2 + (slot * 2 + 1) * ARRU;
        const uint2* gk = g_k2 + (size_t)b * 16 * 2048 + st * 64;
        const uint2* gv = g_v2 + ((size_t)(b * 32 + st)) * 16 * 64;
#pragma unroll
        for (int u = 0; u < 4; u++) {
            const int cid = tid + 128 * u;
            const int p   = cid >> 5;
            const int off = (cid & 31) * 2;
            cpa16(kf + p * KP2 + off, gk + p * 2048 + off);
            cpa16(vf + p * KP2 + off, gv + p * 64 + off);
        }
    };

    for (int half = 0; half < 2; half++) {
        const int qt = half ? blockIdx.x : 31 - blockIdx.x;
        const int rowg = b * TT + qt * 64;
        const int grow1 = qt * 64 + wrow + lg;
        const int grow2 = grow1 + 8;

        // ---- Q fragments ----
        unsigned qh[4][4], ql[4][4];
        {
            const float* q1 = g_q + (rowg + wrow + lg) * DD;
            const float* q2 = q1 + 8 * DD;
#pragma unroll
            for (int c = 0; c < 4; c++) {
                const int cc = 16 * c + 2 * lr;
                float2 a  = *(const float2*)(q1 + cc);
                float2 bq = *(const float2*)(q2 + cc);
                float2 a8 = *(const float2*)(q1 + cc + 8);
                float2 b8 = *(const float2*)(q2 + cc + 8);
                splith2(a.x  * SCL, a.y  * SCL, qh[c][0], ql[c][0]);
                splith2(bq.x * SCL, bq.y * SCL, qh[c][1], ql[c][1]);
                splith2(a8.x * SCL, a8.y * SCL, qh[c][2], ql[c][2]);
                splith2(b8.x * SCL, b8.y * SCL, qh[c][3], ql[c][3]);
            }
        }

        float4 oc[8];
#pragma unroll
        for (int j = 0; j < 8; j++) oc[j] = make_float4(0.f, 0.f, 0.f, 0.f);
        float4 ls = make_float4(0.f, 0.f, 0.f, 0.f);
        float m1 = -1e30f, m2 = -1e30f;

        // compute S for one resident tile into sc
        auto calcS = [&](float4 sc[8], int slot) {
            const uint2* kfb = sm2 + (slot * 2 + 0) * ARRU;
#pragma unroll
            for (int j = 0; j < 8; j++) sc[j] = make_float4(0.f, 0.f, 0.f, 0.f);
#pragma unroll
            for (int c = 0; c < 4; c++) {
                const int kb = (4 * c + lr) * KP2 + lg;
#pragma unroll
                for (int j = 0; j < 8; j++) {
                    const uint2 kk = kfb[kb + 8 * j];
                    mma16h(sc[j], qh[c], kk.x, kk.y);
                    mma16h(sc[j], ql[c], kk.x, kk.y);
                }
            }
        };
        auto maskDiag = [&](float4 sc[8]) {
            const int cbv = qt * 64 + 2 * lr;
#pragma unroll
            for (int j = 0; j < 8; j++) {
                const int c0g = cbv + 8 * j;
                if (c0g     > grow1) sc[j].x = NEG_INF;
                if (c0g + 1 > grow1) sc[j].y = NEG_INF;
                if (c0g     > grow2) sc[j].z = NEG_INF;
                if (c0g + 1 > grow2) sc[j].w = NEG_INF;
            }
        };
        auto redMax = [&](const float4 sc[8], float& rm1, float& rm2) {
#pragma unroll
            for (int j = 0; j < 8; j++) {
                rm1 = fmaxf(rm1, fmaxf(sc[j].x, sc[j].y));
                rm2 = fmaxf(rm2, fmaxf(sc[j].z, sc[j].w));
            }
        };
        auto expP = [&](const float4 sc[8], unsigned pa[8], unsigned pb[8],
                        float mn1, float mn2) {
#pragma unroll
            for (int j = 0; j < 8; j++) {
                pa[j] = h2exp2(packh2(sc[j].x - mn1, sc[j].y - mn1));
                pb[j] = h2exp2(packh2(sc[j].z - mn2, sc[j].w - mn2));
            }
        };
        auto pvAcc = [&](const unsigned pa[8], const unsigned pb[8], int slot) {
            const uint2* vfb = sm2 + (slot * 2 + 1) * ARRU;
#pragma unroll
            for (int c = 0; c < 4; c++) {
                const unsigned ah[4] = {pa[2 * c], pb[2 * c], pa[2 * c + 1], pb[2 * c + 1]};
                const int vb = (4 * c + lr) * KP2 + lg;
#pragma unroll
                for (int j = 0; j < 8; j++) {
                    const uint2 vv = vfb[vb + 8 * j];
                    mma16h(oc[j], ah, vv.x, vv.y);
                }
                mma16h(ls, ah, ONESH2, ONESH2);
            }
        };
        auto rescale = [&](float mn1, float mn2) {
            const float fac1 = ex2(m1 - mn1);
            const float fac2 = ex2(m2 - mn2);
            m1 = mn1; m2 = mn2;
#pragma unroll
            for (int j = 0; j < 8; j++) {
                oc[j].x *= fac1; oc[j].y *= fac1;
                oc[j].z *= fac2; oc[j].w *= fac2;
            }
            ls.x *= fac1;
            ls.z *= fac2;
        };

        const int nchunk = (qt + 2) >> 1;

        __syncthreads();                 // protect smem reuse across halves
        stage64(0, 0);
        if (qt >= 1) stage64(1, 1);
        asm volatile("cp.async.commit_group;" ::: "memory");
        int buf = 0;

        for (int p = 0; p < nchunk; p++) {
            asm volatile("cp.async.wait_group 0;" ::: "memory");
            __syncthreads();
            if (p + 1 < nchunk) {
                const int s2 = 2 * (p + 1);
                stage64((buf ^ 1) * 2 + 0, s2);
                if (s2 + 1 <= qt) stage64((buf ^ 1) * 2 + 1, s2 + 1);
                asm volatile("cp.async.commit_group;" ::: "memory");
            }

            const int stA = 2 * p;
            if (stA + 1 <= qt) {
                // ---- 128-wide block: S_A + S_B, joint softmax ----
                float4 sa[8], sb[8];
                calcS(sa, buf * 2 + 0);
                calcS(sb, buf * 2 + 1);
                if (stA + 1 == qt) maskDiag(sb);

                float rm1 = NEG_INF, rm2 = NEG_INF;
                redMax(sa, rm1, rm2);
                redMax(sb, rm1, rm2);
                rm1 = fmaxf(rm1, __shfl_xor_sync(0xffffffffu, rm1, 1));
                rm1 = fmaxf(rm1, __shfl_xor_sync(0xffffffffu, rm1, 2));
                rm2 = fmaxf(rm2, __shfl_xor_sync(0xffffffffu, rm2, 1));
                rm2 = fmaxf(rm2, __shfl_xor_sync(0xffffffffu, rm2, 2));
                const float mn1 = fmaxf(m1, rm1);
                const float mn2 = fmaxf(m2, rm2);
                rescale(mn1, mn2);

                unsigned pa1[8], pa2[8];
                expP(sa, pa1, pa2, mn1, mn2);
                pvAcc(pa1, pa2, buf * 2 + 0);
                expP(sb, pa1, pa2, mn1, mn2);
                pvAcc(pa1, pa2, buf * 2 + 1);
            } else {
                // ---- single leftover tile (stA == qt, qt even) ----
                float4 sa[8];
                calcS(sa, buf * 2 + 0);
                maskDiag(sa);

                float rm1 = NEG_INF, rm2 = NEG_INF;
                redMax(sa, rm1, rm2);
                rm1 = fmaxf(rm1, __shfl_xor_sync(0xffffffffu, rm1, 1));
                rm1 = fmaxf(rm1, __shfl_xor_sync(0xffffffffu, rm1, 2));
                rm2 = fmaxf(rm2, __shfl_xor_sync(0xffffffffu, rm2, 1));
                rm2 = fmaxf(rm2, __shfl_xor_sync(0xffffffffu, rm2, 2));
                const float mn1 = fmaxf(m1, rm1);
                const float mn2 = fmaxf(m2, rm2);
                rescale(mn1, mn2);

                unsigned pa1[8], pa2[8];
                expP(sa, pa1, pa2, mn1, mn2);
                pvAcc(pa1, pa2, buf * 2 + 0);
            }
            buf ^= 1;
        }

        // ---- epilogue ----
        const float inv1 = 1.0f / ls.x;
        const float inv2 = 1.0f / ls.z;
        const int ob1 = (rowg + wrow + lg) * DD + 2 * lr;
        const int ob2 = ob1 + 8 * DD;
#pragma unroll
        for (int j = 0; j < 8; j++) {
            *(float2*)&out[ob1 + 8 * j] = make_float2(oc[j].x * inv1, oc[j].y * inv1);
            *(float2*)&out[ob2 + 8 * j] = make_float2(oc[j].z * inv2, oc[j].w * inv2);
        }
    }
}

// ---------------------------------------------------------------------------
extern "C" void kernel_launch(void* const* d_in, const int* in_sizes, int n_in,
                              void* d_out, int out_size)
{
    (void)in_sizes; (void)n_in; (void)out_size;
    const float* x  = (const float*)d_in[0];
    const float* Wq = (const float*)d_in[1];
    const float* Wk = (const float*)d_in[2];
    const float* Wv = (const float*)d_in[3];
    float* out = (float*)d_out;

    cudaFuncSetAttribute(proj_kernel,
                         cudaFuncAttributeMaxDynamicSharedMemorySize, PROJ_SMEM);
    cudaFuncSetAttribute(attn_kernel,
                         cudaFuncAttributeMaxDynamicSharedMemorySize, ATTN_SMEM);

    wsplit_kernel<<<192, 192>>>(Wq, Wk, Wv);
    proj_kernel<<<dim3(BB * TT / 128, 2), 256, PROJ_SMEM>>>(x);
    attn_kernel<<<dim3(16, BB), 128, ATTN_SMEM>>>(out);
}